// round 9
// baseline (speedup 1.0000x reference)
#include <cuda_runtime.h>
#include <cuda_fp16.h>
#include <cstdint>

#define NNODES 50000
#define NREL   8
#define NEDGES 100000
#define NIDX   (NREL * NNODES)          // 400000
#define RE     (NREL * NEDGES)          // 800000
#define INPSZ  (NNODES * 128)
#define WSZ    (NREL * 128 * 128)

// ---------------------------------------------------------------------------
// Device scratch
// ---------------------------------------------------------------------------
__device__ __half g_inph[(size_t)INPSZ];              // fp16 inp (12.8 MB)
__device__ __half g_Wh[WSZ];                          // fp16 W
__device__ __half g_Hh[NREL][(size_t)NNODES * 128];   // fp16 H (102.4 MB)
__device__ int    g_cnt[NIDX];
__device__ int    g_cur[NIDX];
__device__ int    g_off[NIDX + 1];
__device__ int    g_bsum[128];
__device__ int    g_bbase[128];
__device__ int2   g_edge[RE];                         // {src, val bits}

__device__ __forceinline__ uint32_t smem_u32(const void* p) {
    uint32_t a;
    asm("{ .reg .u64 t; cvta.to.shared.u64 t, %1; cvt.u32.u64 %0, t; }" : "=r"(a) : "l"(p));
    return a;
}
__device__ __forceinline__ void cp16(uint32_t dst, const void* src, uint32_t bytes) {
    asm volatile("cp.async.cg.shared.global [%0], [%1], 16, %2;"
                 :: "r"(dst), "l"(src), "r"(bytes) : "memory");
}

// ---------------------------------------------------------------------------
// Prep: fp32 -> fp16
// ---------------------------------------------------------------------------
__global__ void k_prep(const float2* __restrict__ inp, const float2* __restrict__ W) {
    int i = blockIdx.x * 256 + threadIdx.x;
    if (i < INPSZ / 2) {
        float2 v = inp[i];
        ((__half2*)g_inph)[i] = __floats2half2_rn(v.x, v.y);
    }
    if (i < WSZ / 2) {
        float2 w = W[i];
        ((__half2*)g_Wh)[i] = __floats2half2_rn(w.x, w.y);
    }
}

// ---------------------------------------------------------------------------
// CSR build (side stream)
// ---------------------------------------------------------------------------
__global__ void k_zero() {
    int i = blockIdx.x * 256 + threadIdx.x;
    if (i < NIDX) { g_cnt[i] = 0; g_cur[i] = 0; }
}
__global__ void k_hist(const int* __restrict__ dst) {
    int tid = blockIdx.x * 256 + threadIdx.x;
    if (tid >= RE) return;
    int r = tid / NEDGES;
    atomicAdd(&g_cnt[r * NNODES + dst[tid]], 1);
}
__device__ __forceinline__ int wscan(int x, int lane) {
    #pragma unroll
    for (int o = 1; o < 32; o <<= 1) {
        int y = __shfl_up_sync(0xffffffffu, x, o);
        if (lane >= o) x += y;
    }
    return x;
}
__global__ void k_scanA() {
    __shared__ int ws[32];
    int t = threadIdx.x, lane = t & 31, wid = t >> 5;
    int base = blockIdx.x * 4096 + t * 4;
    int v[4];
    #pragma unroll
    for (int i = 0; i < 4; i++) v[i] = (base + i < NIDX) ? g_cnt[base + i] : 0;
    v[1] += v[0]; v[2] += v[1]; v[3] += v[2];
    int x = wscan(v[3], lane);
    if (lane == 31) ws[wid] = x;
    __syncthreads();
    if (wid == 0) ws[lane] = wscan(ws[lane], lane);
    __syncthreads();
    int pre = (wid ? ws[wid - 1] : 0) + (x - v[3]);
    #pragma unroll
    for (int i = 0; i < 4; i++)
        if (base + i < NIDX) g_off[base + i + 1] = pre + v[i];
    if (t == 1023) g_bsum[blockIdx.x] = ws[31];
}
__global__ void k_scanB(int nblk) {
    __shared__ int ws[4];
    int t = threadIdx.x, lane = t & 31, wid = t >> 5;
    int v = (t < nblk) ? g_bsum[t] : 0;
    int x = wscan(v, lane);
    if (lane == 31) ws[wid] = x;
    __syncthreads();
    if (t == 0) { int a = 0; for (int i = 0; i < 4; i++) { int tmp = ws[i]; ws[i] = a; a += tmp; } }
    __syncthreads();
    int incl = x + ws[wid];
    if (t < nblk) g_bbase[t] = incl - v;
}
__global__ void k_scanC() {
    int t = threadIdx.x;
    int add = g_bbase[blockIdx.x];
    int base = blockIdx.x * 4096 + t * 4;
    #pragma unroll
    for (int i = 0; i < 4; i++)
        if (base + i < NIDX) g_off[base + i + 1] += add;
    if (blockIdx.x == 0 && t == 0) g_off[0] = 0;
}
__global__ void k_fill(const int* __restrict__ dst, const int* __restrict__ src,
                       const float* __restrict__ vals) {
    int tid = blockIdx.x * 256 + threadIdx.x;
    if (tid >= RE) return;
    int r = tid / NEDGES;
    int idx = r * NNODES + dst[tid];
    int p = atomicAdd(&g_cur[idx], 1);
    int pos = g_off[idx] + p;
    g_edge[pos] = make_int2(src[tid], __float_as_int(vals[tid]));
}

// ---------------------------------------------------------------------------
// GEMM: H[r] = inp_h @ W_r for 4 relations (half), 2 rel/CTA, full-K resident.
// ---------------------------------------------------------------------------
__global__ void __launch_bounds__(256, 2) k_gemm(int half) {
    extern __shared__ __align__(16) char dsm[];
    uint32_t sb = smem_u32(dsm);
    uint32_t ab = sb, bb[2] = { sb + 32768u, sb + 65536u };

    int tid = threadIdx.x;
    int lane = tid & 31, wid = tid >> 5;
    int wm = wid & 1, wn = wid >> 1;
    int m0 = blockIdx.x * 128;
    int rbase = half * 4 + blockIdx.y * 2;

    const __half* A = g_inph;
    #pragma unroll
    for (int it = 0; it < 8; it++) {
        int id = it * 256 + tid;
        int row = id >> 4, c = id & 15;
        int grow = m0 + row;
        uint32_t bytes = (grow < NNODES) ? 16u : 0u;
        const __half* src = A + (size_t)(grow < NNODES ? grow : 0) * 128 + c * 8;
        cp16(ab + row * 256 + ((c ^ (row & 7)) * 16), src, bytes);
    }
    asm volatile("cp.async.commit_group;" ::: "memory");
    #pragma unroll
    for (int rr = 0; rr < 2; rr++) {
        const __half* B = g_Wh + (rbase + rr) * 16384;
        #pragma unroll
        for (int it = 0; it < 8; it++) {
            int id = it * 256 + tid;
            int row = id >> 4, c = id & 15;
            cp16(bb[rr] + row * 256 + ((c ^ (row & 7)) * 16), B + row * 128 + c * 8, 16u);
        }
        asm volatile("cp.async.commit_group;" ::: "memory");
    }

    uint32_t arow = (uint32_t)(wm * 64 + (lane & 15));
    uint32_t axor = arow & 7;
    uint32_t alh  = (uint32_t)(lane >> 4);
    uint32_t abase_l = ab + arow * 256;
    uint32_t brow_l  = (uint32_t)(lane & 15);
    uint32_t bxor    = (uint32_t)(lane & 7);

    asm volatile("cp.async.wait_group 1;" ::: "memory");
    __syncthreads();

    #pragma unroll
    for (int rr = 0; rr < 2; rr++) {
        if (rr == 1) {
            asm volatile("cp.async.wait_group 0;" ::: "memory");
            __syncthreads();
        }
        uint32_t bsb = bb[rr];

        float c[4][4][4];
        #pragma unroll
        for (int i = 0; i < 4; i++)
            #pragma unroll
            for (int j = 0; j < 4; j++)
                c[i][j][0] = c[i][j][1] = c[i][j][2] = c[i][j][3] = 0.f;

        #pragma unroll
        for (int kb = 0; kb < 4; kb++) {
            #pragma unroll
            for (int kk = 0; kk < 2; kk++) {
                uint32_t a[4][4], b[4][2];
                uint32_t ach = (uint32_t)(kb * 4 + kk * 2) + alh;
                #pragma unroll
                for (int i = 0; i < 4; i++) {
                    uint32_t ad = abase_l + (uint32_t)(i * 16 * 256) +
                                  ((ach ^ axor) * 16);
                    asm volatile("ldmatrix.sync.aligned.m8n8.x4.shared.b16 "
                                 "{%0,%1,%2,%3}, [%4];"
                                 : "=r"(a[i][0]), "=r"(a[i][1]),
                                   "=r"(a[i][2]), "=r"(a[i][3])
                                 : "r"(ad));
                }
                uint32_t brow = (uint32_t)(kb * 32 + kk * 16) + brow_l;
                #pragma unroll
                for (int p = 0; p < 2; p++) {
                    uint32_t nch = (uint32_t)(wn * 4 + p * 2) + alh;
                    uint32_t bd = bsb + brow * 256 + ((nch ^ bxor) * 16);
                    asm volatile("ldmatrix.sync.aligned.m8n8.x4.trans.shared.b16 "
                                 "{%0,%1,%2,%3}, [%4];"
                                 : "=r"(b[p*2][0]), "=r"(b[p*2][1]),
                                   "=r"(b[p*2+1][0]), "=r"(b[p*2+1][1])
                                 : "r"(bd));
                }
                #pragma unroll
                for (int i = 0; i < 4; i++)
                    #pragma unroll
                    for (int j = 0; j < 4; j++)
                        asm volatile(
                            "mma.sync.aligned.m16n8k16.row.col.f32.f16.f16.f32 "
                            "{%0,%1,%2,%3}, {%4,%5,%6,%7}, {%8,%9}, {%0,%1,%2,%3};"
                            : "+f"(c[i][j][0]), "+f"(c[i][j][1]),
                              "+f"(c[i][j][2]), "+f"(c[i][j][3])
                            : "r"(a[i][0]), "r"(a[i][1]), "r"(a[i][2]), "r"(a[i][3]),
                              "r"(b[j][0]), "r"(b[j][1]));
            }
        }

        int grp = lane >> 2, tg = lane & 3;
        uint32_t* H = (uint32_t*)g_Hh[rbase + rr];
        #pragma unroll
        for (int i = 0; i < 4; i++) {
            int row0 = m0 + wm * 64 + i * 16 + grp;
            #pragma unroll
            for (int j = 0; j < 4; j++) {
                int nc2 = (wn * 32 + j * 8 + tg * 2) >> 1;
                __half2 lo = __floats2half2_rn(c[i][j][0], c[i][j][1]);
                __half2 hi = __floats2half2_rn(c[i][j][2], c[i][j][3]);
                if (row0 < NNODES)
                    H[(size_t)row0 * 64 + nc2] = *(uint32_t*)&lo;
                if (row0 + 8 < NNODES)
                    H[(size_t)(row0 + 8) * 64 + nc2] = *(uint32_t*)&hi;
            }
        }
    }
}

// ---------------------------------------------------------------------------
// Scatter (half): warp per (node, relation); 8 warps = 2 nodes x 4 relations.
// smem reduction across the 4 relation-warps of each node.
// ---------------------------------------------------------------------------
__global__ void __launch_bounds__(256) k_scatter(int half, float* __restrict__ out) {
    __shared__ float4 red[8][32];
    int wid = threadIdx.x >> 5, lane = threadIdx.x & 31;
    int node = blockIdx.x * 2 + (wid >> 2);
    int r = half * 4 + (wid & 3);

    float4 acc = make_float4(0.f, 0.f, 0.f, 0.f);
    if (node < NNODES) {
        int idx = r * NNODES + node;
        int j = __ldg(&g_off[idx]);
        int e = __ldg(&g_off[idx + 1]);
        const uint2* H2 = (const uint2*)g_Hh[r];
        for (; j + 1 < e; j += 2) {
            int2 e0 = __ldg(&g_edge[j]);
            int2 e1 = __ldg(&g_edge[j + 1]);
            float v0 = __int_as_float(e0.y), v1 = __int_as_float(e1.y);
            uint2 p0 = __ldg(&H2[(size_t)e0.x * 32 + lane]);
            uint2 p1 = __ldg(&H2[(size_t)e1.x * 32 + lane]);
            float2 x0 = __half22float2(*(__half2*)&p0.x);
            float2 y0 = __half22float2(*(__half2*)&p0.y);
            float2 x1 = __half22float2(*(__half2*)&p1.x);
            float2 y1 = __half22float2(*(__half2*)&p1.y);
            acc.x += v0 * x0.x + v1 * x1.x;
            acc.y += v0 * x0.y + v1 * x1.y;
            acc.z += v0 * y0.x + v1 * y1.x;
            acc.w += v0 * y0.y + v1 * y1.y;
        }
        if (j < e) {
            int2 e0 = __ldg(&g_edge[j]);
            float v = __int_as_float(e0.y);
            uint2 p = __ldg(&H2[(size_t)e0.x * 32 + lane]);
            float2 x = __half22float2(*(__half2*)&p.x);
            float2 y = __half22float2(*(__half2*)&p.y);
            acc.x += v * x.x; acc.y += v * x.y;
            acc.z += v * y.x; acc.w += v * y.y;
        }
    }
    red[wid][lane] = acc;
    __syncthreads();
    if ((wid & 3) == 0 && node < NNODES) {
        float4 a = red[wid][lane],     b = red[wid + 1][lane];
        float4 c = red[wid + 2][lane], d = red[wid + 3][lane];
        float4 s = make_float4(a.x + b.x + c.x + d.x, a.y + b.y + c.y + d.y,
                               a.z + b.z + c.z + d.z, a.w + b.w + c.w + d.w);
        float4* o = (float4*)out + (size_t)node * 32 + lane;
        if (half == 0) {
            *o = s;
        } else {
            float4 p = *o;
            *o = make_float4(p.x + s.x, p.y + s.y, p.z + s.z, p.w + s.w);
        }
    }
}

// ---------------------------------------------------------------------------
// Streams/events + smem opt-in (host objects, pre-main)
// ---------------------------------------------------------------------------
static cudaStream_t s2 = nullptr;
static cudaEvent_t  evFork, evG0, evS0;
static bool g_ok = false;

#define GEMM_SMEM 98304

namespace {
struct StreamInit {
    StreamInit() {
        cudaFuncSetAttribute((const void*)k_gemm,
                             cudaFuncAttributeMaxDynamicSharedMemorySize, GEMM_SMEM);
        if (cudaStreamCreateWithFlags(&s2, cudaStreamNonBlocking) != cudaSuccess) return;
        if (cudaEventCreateWithFlags(&evFork, cudaEventDisableTiming) != cudaSuccess) return;
        if (cudaEventCreateWithFlags(&evG0,   cudaEventDisableTiming) != cudaSuccess) return;
        if (cudaEventCreateWithFlags(&evS0,   cudaEventDisableTiming) != cudaSuccess) return;
        g_ok = true;
    }
};
static StreamInit g_si;
}

extern "C" void kernel_launch(void* const* d_in, const int* in_sizes, int n_in,
                              void* d_out, int out_size) {
    const float* inp  = (const float*)d_in[0];
    const int*   src  = (const int*)  d_in[1];
    const int*   dst  = (const int*)  d_in[2];
    const float* vals = (const float*)d_in[3];
    const float* W    = (const float*)d_in[4];
    float* out = (float*)d_out;

    cudaFuncSetAttribute((const void*)k_gemm,
                         cudaFuncAttributeMaxDynamicSharedMemorySize, GEMM_SMEM);

    const int SCAN_BLKS = (NIDX + 4095) / 4096;   // 98
    const int PREP_BLKS = (INPSZ / 2 + 255) / 256;
    dim3 ggrid((NNODES + 127) / 128, 2);          // 391 x 2 (4 rel per launch)
    int  sgrid = (NNODES + 1) / 2;                // 25000 (2 nodes per block)

    if (g_ok) {
        cudaEventRecord(evFork, 0);
        cudaStreamWaitEvent(s2, evFork, 0);

        k_prep<<<PREP_BLKS, 256>>>((const float2*)inp, (const float2*)W);   // 0
        k_zero<<<(NIDX + 255) / 256, 256, 0, s2>>>();                        // 1
        k_hist<<<(RE + 255) / 256, 256, 0, s2>>>(dst);                       // 2
        k_gemm<<<ggrid, 256, GEMM_SMEM>>>(0);                                // 3 (ncu)
        cudaEventRecord(evG0, 0);
        k_scanA<<<SCAN_BLKS, 1024, 0, s2>>>();                               // 4
        k_scanB<<<1, 128, 0, s2>>>(SCAN_BLKS);                               // 5
        k_scanC<<<SCAN_BLKS, 1024, 0, s2>>>();                               // 6
        k_fill <<<(RE + 255) / 256, 256, 0, s2>>>(dst, src, vals);           // 7
        k_gemm<<<ggrid, 256, GEMM_SMEM>>>(1);                                // 8
        cudaStreamWaitEvent(s2, evG0, 0);
        k_scatter<<<sgrid, 256, 0, s2>>>(0, out);                            // 9
        cudaEventRecord(evS0, s2);
        cudaStreamWaitEvent(0, evS0, 0);
        k_scatter<<<sgrid, 256>>>(1, out);                                   // 10
    } else {
        k_prep<<<PREP_BLKS, 256>>>((const float2*)inp, (const float2*)W);
        k_zero<<<(NIDX + 255) / 256, 256>>>();
        k_hist<<<(RE + 255) / 256, 256>>>(dst);
        k_gemm<<<ggrid, 256, GEMM_SMEM>>>(0);
        k_scanA<<<SCAN_BLKS, 1024>>>();
        k_scanB<<<1, 128>>>(SCAN_BLKS);
        k_scanC<<<SCAN_BLKS, 1024>>>();
        k_fill <<<(RE + 255) / 256, 256>>>(dst, src, vals);
        k_gemm<<<ggrid, 256, GEMM_SMEM>>>(1);
        k_scatter<<<sgrid, 256>>>(0, out);
        k_scatter<<<sgrid, 256>>>(1, out);
    }
}

// round 10
// speedup vs baseline: 1.1188x; 1.1188x over previous
#include <cuda_runtime.h>
#include <cuda_fp16.h>
#include <cstdint>

#define NNODES 50000
#define NREL   8
#define NEDGES 100000
#define NIDX   (NREL * NNODES)          // 400000
#define RE     (NREL * NEDGES)          // 800000
#define INPSZ  (NNODES * 128)
#define WSZ    (NREL * 128 * 128)

// ---------------------------------------------------------------------------
// Device scratch
// ---------------------------------------------------------------------------
__device__ __half g_inph[(size_t)INPSZ];              // fp16 inp (12.8 MB)
__device__ __half g_Wh[WSZ];                          // fp16 W
__device__ __half g_Hh[NREL][(size_t)NNODES * 128];   // fp16 H (102.4 MB)
__device__ int    g_cnt[NIDX];
__device__ int    g_cur[NIDX];
__device__ int    g_off[NIDX + 1];
__device__ int    g_bsum[128];
__device__ int    g_bbase[128];
__device__ int2   g_edge[RE];                         // {src, val bits}

__device__ __forceinline__ uint32_t smem_u32(const void* p) {
    uint32_t a;
    asm("{ .reg .u64 t; cvta.to.shared.u64 t, %1; cvt.u32.u64 %0, t; }" : "=r"(a) : "l"(p));
    return a;
}
__device__ __forceinline__ void cp16(uint32_t dst, const void* src, uint32_t bytes) {
    asm volatile("cp.async.cg.shared.global [%0], [%1], 16, %2;"
                 :: "r"(dst), "l"(src), "r"(bytes) : "memory");
}

// ---------------------------------------------------------------------------
// Prep: fp32 -> fp16
// ---------------------------------------------------------------------------
__global__ void k_prep(const float2* __restrict__ inp, const float2* __restrict__ W) {
    int i = blockIdx.x * 256 + threadIdx.x;
    if (i < INPSZ / 2) {
        float2 v = inp[i];
        ((__half2*)g_inph)[i] = __floats2half2_rn(v.x, v.y);
    }
    if (i < WSZ / 2) {
        float2 w = W[i];
        ((__half2*)g_Wh)[i] = __floats2half2_rn(w.x, w.y);
    }
}

// ---------------------------------------------------------------------------
// CSR build (side stream)
// ---------------------------------------------------------------------------
__global__ void k_zero() {
    int i = blockIdx.x * 256 + threadIdx.x;
    if (i < NIDX) { g_cnt[i] = 0; g_cur[i] = 0; }
}
__global__ void k_hist(const int* __restrict__ dst) {
    int tid = blockIdx.x * 256 + threadIdx.x;
    if (tid >= RE) return;
    int r = tid / NEDGES;
    atomicAdd(&g_cnt[r * NNODES + dst[tid]], 1);
}
__device__ __forceinline__ int wscan(int x, int lane) {
    #pragma unroll
    for (int o = 1; o < 32; o <<= 1) {
        int y = __shfl_up_sync(0xffffffffu, x, o);
        if (lane >= o) x += y;
    }
    return x;
}
__global__ void k_scanA() {
    __shared__ int ws[32];
    int t = threadIdx.x, lane = t & 31, wid = t >> 5;
    int base = blockIdx.x * 4096 + t * 4;
    int v[4];
    #pragma unroll
    for (int i = 0; i < 4; i++) v[i] = (base + i < NIDX) ? g_cnt[base + i] : 0;
    v[1] += v[0]; v[2] += v[1]; v[3] += v[2];
    int x = wscan(v[3], lane);
    if (lane == 31) ws[wid] = x;
    __syncthreads();
    if (wid == 0) ws[lane] = wscan(ws[lane], lane);
    __syncthreads();
    int pre = (wid ? ws[wid - 1] : 0) + (x - v[3]);
    #pragma unroll
    for (int i = 0; i < 4; i++)
        if (base + i < NIDX) g_off[base + i + 1] = pre + v[i];
    if (t == 1023) g_bsum[blockIdx.x] = ws[31];
}
__global__ void k_scanB(int nblk) {
    __shared__ int ws[4];
    int t = threadIdx.x, lane = t & 31, wid = t >> 5;
    int v = (t < nblk) ? g_bsum[t] : 0;
    int x = wscan(v, lane);
    if (lane == 31) ws[wid] = x;
    __syncthreads();
    if (t == 0) { int a = 0; for (int i = 0; i < 4; i++) { int tmp = ws[i]; ws[i] = a; a += tmp; } }
    __syncthreads();
    int incl = x + ws[wid];
    if (t < nblk) g_bbase[t] = incl - v;
}
__global__ void k_scanC() {
    int t = threadIdx.x;
    int add = g_bbase[blockIdx.x];
    int base = blockIdx.x * 4096 + t * 4;
    #pragma unroll
    for (int i = 0; i < 4; i++)
        if (base + i < NIDX) g_off[base + i + 1] += add;
    if (blockIdx.x == 0 && t == 0) g_off[0] = 0;
}
__global__ void k_fill(const int* __restrict__ dst, const int* __restrict__ src,
                       const float* __restrict__ vals) {
    int tid = blockIdx.x * 256 + threadIdx.x;
    if (tid >= RE) return;
    int r = tid / NEDGES;
    int idx = r * NNODES + dst[tid];
    int p = atomicAdd(&g_cur[idx], 1);
    int pos = g_off[idx] + p;
    g_edge[pos] = make_int2(src[tid], __float_as_int(vals[tid]));
}

// ---------------------------------------------------------------------------
// GEMM: H[r] = inp_h @ W_r for 4 relations (half), 2 rel/CTA, full-K resident.
// ---------------------------------------------------------------------------
__global__ void __launch_bounds__(256, 2) k_gemm(int half) {
    extern __shared__ __align__(16) char dsm[];
    uint32_t sb = smem_u32(dsm);
    uint32_t ab = sb, bb[2] = { sb + 32768u, sb + 65536u };

    int tid = threadIdx.x;
    int lane = tid & 31, wid = tid >> 5;
    int wm = wid & 1, wn = wid >> 1;
    int m0 = blockIdx.x * 128;
    int rbase = half * 4 + blockIdx.y * 2;

    const __half* A = g_inph;
    #pragma unroll
    for (int it = 0; it < 8; it++) {
        int id = it * 256 + tid;
        int row = id >> 4, c = id & 15;
        int grow = m0 + row;
        uint32_t bytes = (grow < NNODES) ? 16u : 0u;
        const __half* src = A + (size_t)(grow < NNODES ? grow : 0) * 128 + c * 8;
        cp16(ab + row * 256 + ((c ^ (row & 7)) * 16), src, bytes);
    }
    asm volatile("cp.async.commit_group;" ::: "memory");
    #pragma unroll
    for (int rr = 0; rr < 2; rr++) {
        const __half* B = g_Wh + (rbase + rr) * 16384;
        #pragma unroll
        for (int it = 0; it < 8; it++) {
            int id = it * 256 + tid;
            int row = id >> 4, c = id & 15;
            cp16(bb[rr] + row * 256 + ((c ^ (row & 7)) * 16), B + row * 128 + c * 8, 16u);
        }
        asm volatile("cp.async.commit_group;" ::: "memory");
    }

    uint32_t arow = (uint32_t)(wm * 64 + (lane & 15));
    uint32_t axor = arow & 7;
    uint32_t alh  = (uint32_t)(lane >> 4);
    uint32_t abase_l = ab + arow * 256;
    uint32_t brow_l  = (uint32_t)(lane & 15);
    uint32_t bxor    = (uint32_t)(lane & 7);

    asm volatile("cp.async.wait_group 1;" ::: "memory");
    __syncthreads();

    #pragma unroll
    for (int rr = 0; rr < 2; rr++) {
        if (rr == 1) {
            asm volatile("cp.async.wait_group 0;" ::: "memory");
            __syncthreads();
        }
        uint32_t bsb = bb[rr];

        float c[4][4][4];
        #pragma unroll
        for (int i = 0; i < 4; i++)
            #pragma unroll
            for (int j = 0; j < 4; j++)
                c[i][j][0] = c[i][j][1] = c[i][j][2] = c[i][j][3] = 0.f;

        #pragma unroll
        for (int kb = 0; kb < 4; kb++) {
            #pragma unroll
            for (int kk = 0; kk < 2; kk++) {
                uint32_t a[4][4], b[4][2];
                uint32_t ach = (uint32_t)(kb * 4 + kk * 2) + alh;
                #pragma unroll
                for (int i = 0; i < 4; i++) {
                    uint32_t ad = abase_l + (uint32_t)(i * 16 * 256) +
                                  ((ach ^ axor) * 16);
                    asm volatile("ldmatrix.sync.aligned.m8n8.x4.shared.b16 "
                                 "{%0,%1,%2,%3}, [%4];"
                                 : "=r"(a[i][0]), "=r"(a[i][1]),
                                   "=r"(a[i][2]), "=r"(a[i][3])
                                 : "r"(ad));
                }
                uint32_t brow = (uint32_t)(kb * 32 + kk * 16) + brow_l;
                #pragma unroll
                for (int p = 0; p < 2; p++) {
                    uint32_t nch = (uint32_t)(wn * 4 + p * 2) + alh;
                    uint32_t bd = bsb + brow * 256 + ((nch ^ bxor) * 16);
                    asm volatile("ldmatrix.sync.aligned.m8n8.x4.trans.shared.b16 "
                                 "{%0,%1,%2,%3}, [%4];"
                                 : "=r"(b[p*2][0]), "=r"(b[p*2][1]),
                                   "=r"(b[p*2+1][0]), "=r"(b[p*2+1][1])
                                 : "r"(bd));
                }
                #pragma unroll
                for (int i = 0; i < 4; i++)
                    #pragma unroll
                    for (int j = 0; j < 4; j++)
                        asm volatile(
                            "mma.sync.aligned.m16n8k16.row.col.f32.f16.f16.f32 "
                            "{%0,%1,%2,%3}, {%4,%5,%6,%7}, {%8,%9}, {%0,%1,%2,%3};"
                            : "+f"(c[i][j][0]), "+f"(c[i][j][1]),
                              "+f"(c[i][j][2]), "+f"(c[i][j][3])
                            : "r"(a[i][0]), "r"(a[i][1]), "r"(a[i][2]), "r"(a[i][3]),
                              "r"(b[j][0]), "r"(b[j][1]));
            }
        }

        int grp = lane >> 2, tg = lane & 3;
        uint32_t* H = (uint32_t*)g_Hh[rbase + rr];
        #pragma unroll
        for (int i = 0; i < 4; i++) {
            int row0 = m0 + wm * 64 + i * 16 + grp;
            #pragma unroll
            for (int j = 0; j < 4; j++) {
                int nc2 = (wn * 32 + j * 8 + tg * 2) >> 1;
                __half2 lo = __floats2half2_rn(c[i][j][0], c[i][j][1]);
                __half2 hi = __floats2half2_rn(c[i][j][2], c[i][j][3]);
                if (row0 < NNODES)
                    H[(size_t)row0 * 64 + nc2] = *(uint32_t*)&lo;
                if (row0 + 8 < NNODES)
                    H[(size_t)(row0 + 8) * 64 + nc2] = *(uint32_t*)&hi;
            }
        }
    }
}

// ---------------------------------------------------------------------------
// Scatter (half): warp per node (R8 mapping), software-pipelined across the
// 4 relation cursors: each round has 4 H loads + 4 next-edge loads in flight.
// ---------------------------------------------------------------------------
__global__ void __launch_bounds__(256) k_scatter(int half, float* __restrict__ out) {
    int n = blockIdx.x * 8 + (threadIdx.x >> 5);
    int lane = threadIdx.x & 31;
    if (n >= NNODES) return;

    int rb = half * 4;
    int jp[4], je[4];
    #pragma unroll
    for (int q = 0; q < 4; q++) {
        int idx = (rb + q) * NNODES + n;
        jp[q] = __ldg(&g_off[idx]);
        je[q] = __ldg(&g_off[idx + 1]);
    }

    const uint2* H2[4];
    #pragma unroll
    for (int q = 0; q < 4; q++) H2[q] = (const uint2*)g_Hh[rb + q];

    float4 acc;
    if (half == 0) acc = make_float4(0.f, 0.f, 0.f, 0.f);
    else           acc = ((float4*)out)[(size_t)n * 32 + lane];

    // prime: first edge of each relation
    int2 ed[4];
    bool act[4];
    #pragma unroll
    for (int q = 0; q < 4; q++) {
        act[q] = (jp[q] < je[q]);
        if (act[q]) { ed[q] = __ldg(&g_edge[jp[q]]); jp[q]++; }
    }

    for (;;) {
        // issue H loads for current edges
        uint2 p[4];
        #pragma unroll
        for (int q = 0; q < 4; q++)
            if (act[q]) p[q] = __ldg(&H2[q][(size_t)ed[q].x * 32 + lane]);

        // prefetch next edges (independent of p[])
        int2 ed2[4];
        bool act2[4];
        #pragma unroll
        for (int q = 0; q < 4; q++) {
            act2[q] = (jp[q] < je[q]);
            if (act2[q]) { ed2[q] = __ldg(&g_edge[jp[q]]); jp[q]++; }
        }

        // consume H
        #pragma unroll
        for (int q = 0; q < 4; q++) {
            if (act[q]) {
                float v = __int_as_float(ed[q].y);
                float2 x = __half22float2(*(__half2*)&p[q].x);
                float2 y = __half22float2(*(__half2*)&p[q].y);
                acc.x += v * x.x; acc.y += v * x.y;
                acc.z += v * y.x; acc.w += v * y.y;
            }
        }

        bool any = false;
        #pragma unroll
        for (int q = 0; q < 4; q++) { act[q] = act2[q]; ed[q] = ed2[q]; any |= act2[q]; }
        if (!any) break;
    }

    ((float4*)out)[(size_t)n * 32 + lane] = acc;
}

// ---------------------------------------------------------------------------
// Streams/events + smem opt-in (host objects, pre-main)
// ---------------------------------------------------------------------------
static cudaStream_t s2 = nullptr;
static cudaEvent_t  evFork, evG0, evS0;
static bool g_ok = false;

#define GEMM_SMEM 98304

namespace {
struct StreamInit {
    StreamInit() {
        cudaFuncSetAttribute((const void*)k_gemm,
                             cudaFuncAttributeMaxDynamicSharedMemorySize, GEMM_SMEM);
        if (cudaStreamCreateWithFlags(&s2, cudaStreamNonBlocking) != cudaSuccess) return;
        if (cudaEventCreateWithFlags(&evFork, cudaEventDisableTiming) != cudaSuccess) return;
        if (cudaEventCreateWithFlags(&evG0,   cudaEventDisableTiming) != cudaSuccess) return;
        if (cudaEventCreateWithFlags(&evS0,   cudaEventDisableTiming) != cudaSuccess) return;
        g_ok = true;
    }
};
static StreamInit g_si;
}

extern "C" void kernel_launch(void* const* d_in, const int* in_sizes, int n_in,
                              void* d_out, int out_size) {
    const float* inp  = (const float*)d_in[0];
    const int*   src  = (const int*)  d_in[1];
    const int*   dst  = (const int*)  d_in[2];
    const float* vals = (const float*)d_in[3];
    const float* W    = (const float*)d_in[4];
    float* out = (float*)d_out;

    cudaFuncSetAttribute((const void*)k_gemm,
                         cudaFuncAttributeMaxDynamicSharedMemorySize, GEMM_SMEM);

    const int SCAN_BLKS = (NIDX + 4095) / 4096;   // 98
    const int PREP_BLKS = (INPSZ / 2 + 255) / 256;
    dim3 ggrid((NNODES + 127) / 128, 2);          // 391 x 2 (4 rel per launch)
    int  sgrid = (NNODES + 7) / 8;                // warp per node

    if (g_ok) {
        cudaEventRecord(evFork, 0);
        cudaStreamWaitEvent(s2, evFork, 0);

        k_prep<<<PREP_BLKS, 256>>>((const float2*)inp, (const float2*)W);   // 0
        k_zero<<<(NIDX + 255) / 256, 256, 0, s2>>>();                        // 1
        k_hist<<<(RE + 255) / 256, 256, 0, s2>>>(dst);                       // 2
        k_gemm<<<ggrid, 256, GEMM_SMEM>>>(0);                                // 3 (ncu)
        cudaEventRecord(evG0, 0);
        k_scanA<<<SCAN_BLKS, 1024, 0, s2>>>();                               // 4
        k_scanB<<<1, 128, 0, s2>>>(SCAN_BLKS);                               // 5
        k_scanC<<<SCAN_BLKS, 1024, 0, s2>>>();                               // 6
        k_fill <<<(RE + 255) / 256, 256, 0, s2>>>(dst, src, vals);           // 7
        k_gemm<<<ggrid, 256, GEMM_SMEM>>>(1);                                // 8
        cudaStreamWaitEvent(s2, evG0, 0);
        k_scatter<<<sgrid, 256, 0, s2>>>(0, out);                            // 9
        cudaEventRecord(evS0, s2);
        cudaStreamWaitEvent(0, evS0, 0);
        k_scatter<<<sgrid, 256>>>(1, out);                                   // 10
    } else {
        k_prep<<<PREP_BLKS, 256>>>((const float2*)inp, (const float2*)W);
        k_zero<<<(NIDX + 255) / 256, 256>>>();
        k_hist<<<(RE + 255) / 256, 256>>>(dst);
        k_gemm<<<ggrid, 256, GEMM_SMEM>>>(0);
        k_scanA<<<SCAN_BLKS, 1024>>>();
        k_scanB<<<1, 128>>>(SCAN_BLKS);
        k_scanC<<<SCAN_BLKS, 1024>>>();
        k_fill <<<(RE + 255) / 256, 256>>>(dst, src, vals);
        k_gemm<<<ggrid, 256, GEMM_SMEM>>>(1);
        k_scatter<<<sgrid, 256>>>(0, out);
        k_scatter<<<sgrid, 256>>>(1, out);
    }
}

// round 11
// speedup vs baseline: 1.3573x; 1.2132x over previous
#include <cuda_runtime.h>
#include <cuda_fp16.h>
#include <cstdint>

#define NNODES 50000
#define NREL   8
#define NEDGES 100000
#define NIDX   (NREL * NNODES)          // 400000
#define RE     (NREL * NEDGES)          // 800000
#define INPSZ  (NNODES * 128)
#define WSZ    (NREL * 128 * 128)

// ---------------------------------------------------------------------------
// Device scratch
// ---------------------------------------------------------------------------
__device__ __half g_inph[(size_t)INPSZ];              // fp16 inp (12.8 MB)
__device__ __half g_Wh[WSZ];                          // fp16 W
__device__ __half g_Hh[NREL][(size_t)NNODES * 128];   // fp16 H (102.4 MB)
__device__ int    g_cnt[NIDX];
__device__ int    g_cur[NIDX];
__device__ int    g_off[NIDX + 1];
__device__ int    g_bsum[128];
__device__ int    g_bbase[128];
__device__ int2   g_edge[RE];                         // {src, val bits}

__device__ __forceinline__ uint32_t smem_u32(const void* p) {
    uint32_t a;
    asm("{ .reg .u64 t; cvta.to.shared.u64 t, %1; cvt.u32.u64 %0, t; }" : "=r"(a) : "l"(p));
    return a;
}
__device__ __forceinline__ void cp16(uint32_t dst, const void* src, uint32_t bytes) {
    asm volatile("cp.async.cg.shared.global [%0], [%1], 16, %2;"
                 :: "r"(dst), "l"(src), "r"(bytes) : "memory");
}

// ---------------------------------------------------------------------------
// Prep: fp32 -> fp16
// ---------------------------------------------------------------------------
__global__ void k_prep(const float2* __restrict__ inp, const float2* __restrict__ W) {
    int i = blockIdx.x * 256 + threadIdx.x;
    if (i < INPSZ / 2) {
        float2 v = inp[i];
        ((__half2*)g_inph)[i] = __floats2half2_rn(v.x, v.y);
    }
    if (i < WSZ / 2) {
        float2 w = W[i];
        ((__half2*)g_Wh)[i] = __floats2half2_rn(w.x, w.y);
    }
}

// ---------------------------------------------------------------------------
// CSR build (side stream)
// ---------------------------------------------------------------------------
__global__ void k_zero() {
    int i = blockIdx.x * 256 + threadIdx.x;
    if (i < NIDX) { g_cnt[i] = 0; g_cur[i] = 0; }
}
__global__ void k_hist(const int* __restrict__ dst) {
    int tid = blockIdx.x * 256 + threadIdx.x;
    if (tid >= RE) return;
    int r = tid / NEDGES;
    atomicAdd(&g_cnt[r * NNODES + dst[tid]], 1);
}
__device__ __forceinline__ int wscan(int x, int lane) {
    #pragma unroll
    for (int o = 1; o < 32; o <<= 1) {
        int y = __shfl_up_sync(0xffffffffu, x, o);
        if (lane >= o) x += y;
    }
    return x;
}
__global__ void k_scanA() {
    __shared__ int ws[32];
    int t = threadIdx.x, lane = t & 31, wid = t >> 5;
    int base = blockIdx.x * 4096 + t * 4;
    int v[4];
    #pragma unroll
    for (int i = 0; i < 4; i++) v[i] = (base + i < NIDX) ? g_cnt[base + i] : 0;
    v[1] += v[0]; v[2] += v[1]; v[3] += v[2];
    int x = wscan(v[3], lane);
    if (lane == 31) ws[wid] = x;
    __syncthreads();
    if (wid == 0) ws[lane] = wscan(ws[lane], lane);
    __syncthreads();
    int pre = (wid ? ws[wid - 1] : 0) + (x - v[3]);
    #pragma unroll
    for (int i = 0; i < 4; i++)
        if (base + i < NIDX) g_off[base + i + 1] = pre + v[i];
    if (t == 1023) g_bsum[blockIdx.x] = ws[31];
}
__global__ void k_scanB(int nblk) {
    __shared__ int ws[4];
    int t = threadIdx.x, lane = t & 31, wid = t >> 5;
    int v = (t < nblk) ? g_bsum[t] : 0;
    int x = wscan(v, lane);
    if (lane == 31) ws[wid] = x;
    __syncthreads();
    if (t == 0) { int a = 0; for (int i = 0; i < 4; i++) { int tmp = ws[i]; ws[i] = a; a += tmp; } }
    __syncthreads();
    int incl = x + ws[wid];
    if (t < nblk) g_bbase[t] = incl - v;
}
__global__ void k_scanC() {
    int t = threadIdx.x;
    int add = g_bbase[blockIdx.x];
    int base = blockIdx.x * 4096 + t * 4;
    #pragma unroll
    for (int i = 0; i < 4; i++)
        if (base + i < NIDX) g_off[base + i + 1] += add;
    if (blockIdx.x == 0 && t == 0) g_off[0] = 0;
}
__global__ void k_fill(const int* __restrict__ dst, const int* __restrict__ src,
                       const float* __restrict__ vals) {
    int tid = blockIdx.x * 256 + threadIdx.x;
    if (tid >= RE) return;
    int r = tid / NEDGES;
    int idx = r * NNODES + dst[tid];
    int p = atomicAdd(&g_cur[idx], 1);
    int pos = g_off[idx] + p;
    g_edge[pos] = make_int2(src[tid], __float_as_int(vals[tid]));
}

// ---------------------------------------------------------------------------
// GEMM: H[r] = inp_h @ W_r, 2 rel/CTA, full-K resident.
// 128 threads = 4 warps (2M x 2N), warp tile 64x64, CTA tile 128x128.
// smem 96KB: A @0, B0 @32768, B1 @65536 (XOR-swizzled 16B cols, 256B rows).
// 8 LDSM.x4 per 32 MMA per warp-k16 (3x less smem traffic than 64x32 tile).
// ---------------------------------------------------------------------------
__global__ void __launch_bounds__(128, 2) k_gemm(int half) {
    extern __shared__ __align__(16) char dsm[];
    uint32_t sb = smem_u32(dsm);
    uint32_t ab = sb, bb[2] = { sb + 32768u, sb + 65536u };

    int tid = threadIdx.x;
    int lane = tid & 31, wid = tid >> 5;          // 4 warps
    int wm = wid & 1, wn = wid >> 1;              // 2M x 2N
    int m0 = blockIdx.x * 128;
    int rbase = half * 4 + blockIdx.y * 2;

    // ---- prologue: async-load full A, B0, B1 (3 commit groups) ----
    const __half* A = g_inph;
    #pragma unroll
    for (int it = 0; it < 16; it++) {
        int id = it * 128 + tid;                  // 2048 16B-chunks
        int row = id >> 4, c = id & 15;
        int grow = m0 + row;
        uint32_t bytes = (grow < NNODES) ? 16u : 0u;
        const __half* src = A + (size_t)(grow < NNODES ? grow : 0) * 128 + c * 8;
        cp16(ab + row * 256 + ((c ^ (row & 7)) * 16), src, bytes);
    }
    asm volatile("cp.async.commit_group;" ::: "memory");
    #pragma unroll
    for (int rr = 0; rr < 2; rr++) {
        const __half* B = g_Wh + (rbase + rr) * 16384;
        #pragma unroll
        for (int it = 0; it < 16; it++) {
            int id = it * 128 + tid;
            int row = id >> 4, c = id & 15;
            cp16(bb[rr] + row * 256 + ((c ^ (row & 7)) * 16), B + row * 128 + c * 8, 16u);
        }
        asm volatile("cp.async.commit_group;" ::: "memory");
    }

    // per-lane ldmatrix address pieces
    uint32_t arow = (uint32_t)(wm * 64 + (lane & 15));
    uint32_t axor = arow & 7;
    uint32_t alh  = (uint32_t)(lane >> 4);
    uint32_t abase_l = ab + arow * 256;
    uint32_t brow_l  = (uint32_t)(lane & 15);
    uint32_t bxor    = (uint32_t)(lane & 7);

    asm volatile("cp.async.wait_group 1;" ::: "memory");   // A + B0 ready
    __syncthreads();

    #pragma unroll
    for (int rr = 0; rr < 2; rr++) {
        if (rr == 1) {
            asm volatile("cp.async.wait_group 0;" ::: "memory");
            __syncthreads();
        }
        uint32_t bsb = bb[rr];

        float c[4][8][4];                          // 128 accum regs
        #pragma unroll
        for (int i = 0; i < 4; i++)
            #pragma unroll
            for (int j = 0; j < 8; j++)
                c[i][j][0] = c[i][j][1] = c[i][j][2] = c[i][j][3] = 0.f;

        #pragma unroll
        for (int k16 = 0; k16 < 8; k16++) {
            uint32_t a[4][4], b[8][2];
            uint32_t ach = (uint32_t)(k16 * 2) + alh;
            #pragma unroll
            for (int i = 0; i < 4; i++) {
                uint32_t ad = abase_l + (uint32_t)(i * 16 * 256) +
                              ((ach ^ axor) * 16);
                asm volatile("ldmatrix.sync.aligned.m8n8.x4.shared.b16 "
                             "{%0,%1,%2,%3}, [%4];"
                             : "=r"(a[i][0]), "=r"(a[i][1]),
                               "=r"(a[i][2]), "=r"(a[i][3])
                             : "r"(ad));
            }
            uint32_t brow = (uint32_t)(k16 * 16) + brow_l;
            #pragma unroll
            for (int p = 0; p < 4; p++) {
                uint32_t nch = (uint32_t)(wn * 8 + p * 2) + alh;
                uint32_t bd = bsb + brow * 256 + ((nch ^ bxor) * 16);
                asm volatile("ldmatrix.sync.aligned.m8n8.x4.trans.shared.b16 "
                             "{%0,%1,%2,%3}, [%4];"
                             : "=r"(b[p*2][0]), "=r"(b[p*2][1]),
                               "=r"(b[p*2+1][0]), "=r"(b[p*2+1][1])
                             : "r"(bd));
            }
            #pragma unroll
            for (int i = 0; i < 4; i++)
                #pragma unroll
                for (int j = 0; j < 8; j++)
                    asm volatile(
                        "mma.sync.aligned.m16n8k16.row.col.f32.f16.f16.f32 "
                        "{%0,%1,%2,%3}, {%4,%5,%6,%7}, {%8,%9}, {%0,%1,%2,%3};"
                        : "+f"(c[i][j][0]), "+f"(c[i][j][1]),
                          "+f"(c[i][j][2]), "+f"(c[i][j][3])
                        : "r"(a[i][0]), "r"(a[i][1]), "r"(a[i][2]), "r"(a[i][3]),
                          "r"(b[j][0]), "r"(b[j][1]));
        }

        // epilogue -> fp16 H[rbase+rr]
        int grp = lane >> 2, tg = lane & 3;
        uint32_t* H = (uint32_t*)g_Hh[rbase + rr];
        #pragma unroll
        for (int i = 0; i < 4; i++) {
            int row0 = m0 + wm * 64 + i * 16 + grp;
            #pragma unroll
            for (int j = 0; j < 8; j++) {
                int nc2 = (wn * 64 + j * 8 + tg * 2) >> 1;
                __half2 lo = __floats2half2_rn(c[i][j][0], c[i][j][1]);
                __half2 hi = __floats2half2_rn(c[i][j][2], c[i][j][3]);
                if (row0 < NNODES)
                    H[(size_t)row0 * 64 + nc2] = *(uint32_t*)&lo;
                if (row0 + 8 < NNODES)
                    H[(size_t)(row0 + 8) * 64 + nc2] = *(uint32_t*)&hi;
            }
        }
    }
}

// ---------------------------------------------------------------------------
// Scatter (half): warp per node, R8 structure (serial relations, x2 unroll).
// ---------------------------------------------------------------------------
__global__ void __launch_bounds__(256) k_scatter(int half, float* __restrict__ out) {
    int n = blockIdx.x * 8 + (threadIdx.x >> 5);
    int lane = threadIdx.x & 31;
    if (n >= NNODES) return;

    int rb = half * 4;
    int j0[4], j1[4];
    #pragma unroll
    for (int q = 0; q < 4; q++) {
        int idx = (rb + q) * NNODES + n;
        j0[q] = __ldg(&g_off[idx]);
        j1[q] = __ldg(&g_off[idx + 1]);
    }

    float4 acc;
    if (half == 0) acc = make_float4(0.f, 0.f, 0.f, 0.f);
    else           acc = ((float4*)out)[(size_t)n * 32 + lane];

    #pragma unroll
    for (int q = 0; q < 4; q++) {
        const uint2* H2 = (const uint2*)g_Hh[rb + q];
        int j = j0[q], e = j1[q];
        for (; j + 1 < e; j += 2) {
            int2 e0 = __ldg(&g_edge[j]);
            int2 e1 = __ldg(&g_edge[j + 1]);
            float v0 = __int_as_float(e0.y), v1 = __int_as_float(e1.y);
            uint2 p0 = __ldg(&H2[(size_t)e0.x * 32 + lane]);
            uint2 p1 = __ldg(&H2[(size_t)e1.x * 32 + lane]);
            float2 x0 = __half22float2(*(__half2*)&p0.x);
            float2 y0 = __half22float2(*(__half2*)&p0.y);
            float2 x1 = __half22float2(*(__half2*)&p1.x);
            float2 y1 = __half22float2(*(__half2*)&p1.y);
            acc.x += v0 * x0.x + v1 * x1.x;
            acc.y += v0 * x0.y + v1 * x1.y;
            acc.z += v0 * y0.x + v1 * y1.x;
            acc.w += v0 * y0.y + v1 * y1.y;
        }
        if (j < e) {
            int2 e0 = __ldg(&g_edge[j]);
            float v = __int_as_float(e0.y);
            uint2 p = __ldg(&H2[(size_t)e0.x * 32 + lane]);
            float2 x = __half22float2(*(__half2*)&p.x);
            float2 y = __half22float2(*(__half2*)&p.y);
            acc.x += v * x.x; acc.y += v * x.y;
            acc.z += v * y.x; acc.w += v * y.y;
        }
    }
    ((float4*)out)[(size_t)n * 32 + lane] = acc;
}

// ---------------------------------------------------------------------------
// Streams/events + smem opt-in (host objects, pre-main)
// ---------------------------------------------------------------------------
static cudaStream_t s2 = nullptr;
static cudaEvent_t  evFork, evG0, evS0;
static bool g_ok = false;

#define GEMM_SMEM 98304

namespace {
struct StreamInit {
    StreamInit() {
        cudaFuncSetAttribute((const void*)k_gemm,
                             cudaFuncAttributeMaxDynamicSharedMemorySize, GEMM_SMEM);
        if (cudaStreamCreateWithFlags(&s2, cudaStreamNonBlocking) != cudaSuccess) return;
        if (cudaEventCreateWithFlags(&evFork, cudaEventDisableTiming) != cudaSuccess) return;
        if (cudaEventCreateWithFlags(&evG0,   cudaEventDisableTiming) != cudaSuccess) return;
        if (cudaEventCreateWithFlags(&evS0,   cudaEventDisableTiming) != cudaSuccess) return;
        g_ok = true;
    }
};
static StreamInit g_si;
}

extern "C" void kernel_launch(void* const* d_in, const int* in_sizes, int n_in,
                              void* d_out, int out_size) {
    const float* inp  = (const float*)d_in[0];
    const int*   src  = (const int*)  d_in[1];
    const int*   dst  = (const int*)  d_in[2];
    const float* vals = (const float*)d_in[3];
    const float* W    = (const float*)d_in[4];
    float* out = (float*)d_out;

    cudaFuncSetAttribute((const void*)k_gemm,
                         cudaFuncAttributeMaxDynamicSharedMemorySize, GEMM_SMEM);

    const int SCAN_BLKS = (NIDX + 4095) / 4096;   // 98
    const int PREP_BLKS = (INPSZ / 2 + 255) / 256;
    dim3 ggrid((NNODES + 127) / 128, 2);          // 391 x 2 (4 rel per launch)
    int  sgrid = (NNODES + 7) / 8;                // warp per node

    if (g_ok) {
        cudaEventRecord(evFork, 0);
        cudaStreamWaitEvent(s2, evFork, 0);

        k_prep<<<PREP_BLKS, 256>>>((const float2*)inp, (const float2*)W);   // 0
        k_zero<<<(NIDX + 255) / 256, 256, 0, s2>>>();                        // 1
        k_hist<<<(RE + 255) / 256, 256, 0, s2>>>(dst);                       // 2
        k_gemm<<<ggrid, 128, GEMM_SMEM>>>(0);                                // 3 (ncu)
        cudaEventRecord(evG0, 0);
        k_scanA<<<SCAN_BLKS, 1024, 0, s2>>>();                               // 4
        k_scanB<<<1, 128, 0, s2>>>(SCAN_BLKS);                               // 5
        k_scanC<<<SCAN_BLKS, 1024, 0, s2>>>();                               // 6
        k_fill <<<(RE + 255) / 256, 256, 0, s2>>>(dst, src, vals);           // 7
        k_gemm<<<ggrid, 128, GEMM_SMEM>>>(1);                                // 8
        cudaStreamWaitEvent(s2, evG0, 0);
        k_scatter<<<sgrid, 256, 0, s2>>>(0, out);                            // 9
        cudaEventRecord(evS0, s2);
        cudaStreamWaitEvent(0, evS0, 0);
        k_scatter<<<sgrid, 256>>>(1, out);                                   // 10
    } else {
        k_prep<<<PREP_BLKS, 256>>>((const float2*)inp, (const float2*)W);
        k_zero<<<(NIDX + 255) / 256, 256>>>();
        k_hist<<<(RE + 255) / 256, 256>>>(dst);
        k_gemm<<<ggrid, 128, GEMM_SMEM>>>(0);
        k_scanA<<<SCAN_BLKS, 1024>>>();
        k_scanB<<<1, 128>>>(SCAN_BLKS);
        k_scanC<<<SCAN_BLKS, 1024>>>();
        k_fill <<<(RE + 255) / 256, 256>>>(dst, src, vals);
        k_gemm<<<ggrid, 128, GEMM_SMEM>>>(1);
        k_scatter<<<sgrid, 256>>>(0, out);
        k_scatter<<<sgrid, 256>>>(1, out);
    }
}

// round 12
// speedup vs baseline: 1.5161x; 1.1170x over previous
#include <cuda_runtime.h>
#include <cuda_fp16.h>
#include <cstdint>

#define NNODES 50000
#define NREL   8
#define NEDGES 100000
#define NIDX   (NREL * NNODES)          // 400000
#define RE     (NREL * NEDGES)          // 800000
#define INPSZ  (NNODES * 128)
#define WSZ    (NREL * 128 * 128)

// ---------------------------------------------------------------------------
// Device scratch
// ---------------------------------------------------------------------------
__device__ __half g_inph[(size_t)INPSZ];                  // fp16 inp (12.8 MB)
__device__ __half g_Wh[WSZ];                              // fp16 W
__device__ __half g_Hh[(size_t)NREL * NNODES * 128];      // flat fp16 H (102.4 MB)
__device__ int    g_cnt[NIDX];
__device__ int    g_cur[NIDX];
__device__ int    g_off[NIDX + 1];
__device__ int    g_bsum[128];
__device__ int    g_bbase[128];
__device__ int2   g_edge[RE];          // {r*NNODES + src, val bits}

__device__ __forceinline__ uint32_t smem_u32(const void* p) {
    uint32_t a;
    asm("{ .reg .u64 t; cvta.to.shared.u64 t, %1; cvt.u32.u64 %0, t; }" : "=r"(a) : "l"(p));
    return a;
}
__device__ __forceinline__ void cp16(uint32_t dst, const void* src, uint32_t bytes) {
    asm volatile("cp.async.cg.shared.global [%0], [%1], 16, %2;"
                 :: "r"(dst), "l"(src), "r"(bytes) : "memory");
}

// ---------------------------------------------------------------------------
// Prep: fp32 -> fp16
// ---------------------------------------------------------------------------
__global__ void k_prep(const float2* __restrict__ inp, const float2* __restrict__ W) {
    int i = blockIdx.x * 256 + threadIdx.x;
    if (i < INPSZ / 2) {
        float2 v = inp[i];
        ((__half2*)g_inph)[i] = __floats2half2_rn(v.x, v.y);
    }
    if (i < WSZ / 2) {
        float2 w = W[i];
        ((__half2*)g_Wh)[i] = __floats2half2_rn(w.x, w.y);
    }
}

// ---------------------------------------------------------------------------
// CSR build (side stream) — indexed by (node, relation): idx = n*8 + r
// ---------------------------------------------------------------------------
__global__ void k_zero() {
    int i = blockIdx.x * 256 + threadIdx.x;
    if (i < NIDX) { g_cnt[i] = 0; g_cur[i] = 0; }
}
__global__ void k_hist(const int* __restrict__ dst) {
    int tid = blockIdx.x * 256 + threadIdx.x;
    if (tid >= RE) return;
    int r = tid / NEDGES;
    atomicAdd(&g_cnt[dst[tid] * 8 + r], 1);
}
__device__ __forceinline__ int wscan(int x, int lane) {
    #pragma unroll
    for (int o = 1; o < 32; o <<= 1) {
        int y = __shfl_up_sync(0xffffffffu, x, o);
        if (lane >= o) x += y;
    }
    return x;
}
__global__ void k_scanA() {
    __shared__ int ws[32];
    int t = threadIdx.x, lane = t & 31, wid = t >> 5;
    int base = blockIdx.x * 4096 + t * 4;
    int v[4];
    #pragma unroll
    for (int i = 0; i < 4; i++) v[i] = (base + i < NIDX) ? g_cnt[base + i] : 0;
    v[1] += v[0]; v[2] += v[1]; v[3] += v[2];
    int x = wscan(v[3], lane);
    if (lane == 31) ws[wid] = x;
    __syncthreads();
    if (wid == 0) ws[lane] = wscan(ws[lane], lane);
    __syncthreads();
    int pre = (wid ? ws[wid - 1] : 0) + (x - v[3]);
    #pragma unroll
    for (int i = 0; i < 4; i++)
        if (base + i < NIDX) g_off[base + i + 1] = pre + v[i];
    if (t == 1023) g_bsum[blockIdx.x] = ws[31];
}
__global__ void k_scanB(int nblk) {
    __shared__ int ws[4];
    int t = threadIdx.x, lane = t & 31, wid = t >> 5;
    int v = (t < nblk) ? g_bsum[t] : 0;
    int x = wscan(v, lane);
    if (lane == 31) ws[wid] = x;
    __syncthreads();
    if (t == 0) { int a = 0; for (int i = 0; i < 4; i++) { int tmp = ws[i]; ws[i] = a; a += tmp; } }
    __syncthreads();
    int incl = x + ws[wid];
    if (t < nblk) g_bbase[t] = incl - v;
}
__global__ void k_scanC() {
    int t = threadIdx.x;
    int add = g_bbase[blockIdx.x];
    int base = blockIdx.x * 4096 + t * 4;
    #pragma unroll
    for (int i = 0; i < 4; i++)
        if (base + i < NIDX) g_off[base + i + 1] += add;
    if (blockIdx.x == 0 && t == 0) g_off[0] = 0;
}
__global__ void k_fill(const int* __restrict__ dst, const int* __restrict__ src,
                       const float* __restrict__ vals) {
    int tid = blockIdx.x * 256 + threadIdx.x;
    if (tid >= RE) return;
    int r = tid / NEDGES;
    int idx = dst[tid] * 8 + r;
    int p = atomicAdd(&g_cur[idx], 1);
    int pos = g_off[idx] + p;
    g_edge[pos] = make_int2(r * NNODES + src[tid], __float_as_int(vals[tid]));
}

// ---------------------------------------------------------------------------
// GEMM: H[r] = inp_h @ W_r, 2 rel/CTA, full-K resident (unchanged from R11).
// 128 threads = 4 warps (2M x 2N), warp tile 64x64, CTA tile 128x128.
// ---------------------------------------------------------------------------
__global__ void __launch_bounds__(128, 2) k_gemm(int half) {
    extern __shared__ __align__(16) char dsm[];
    uint32_t sb = smem_u32(dsm);
    uint32_t ab = sb, bb[2] = { sb + 32768u, sb + 65536u };

    int tid = threadIdx.x;
    int lane = tid & 31, wid = tid >> 5;
    int wm = wid & 1, wn = wid >> 1;
    int m0 = blockIdx.x * 128;
    int rbase = half * 4 + blockIdx.y * 2;

    const __half* A = g_inph;
    #pragma unroll
    for (int it = 0; it < 16; it++) {
        int id = it * 128 + tid;
        int row = id >> 4, c = id & 15;
        int grow = m0 + row;
        uint32_t bytes = (grow < NNODES) ? 16u : 0u;
        const __half* src = A + (size_t)(grow < NNODES ? grow : 0) * 128 + c * 8;
        cp16(ab + row * 256 + ((c ^ (row & 7)) * 16), src, bytes);
    }
    asm volatile("cp.async.commit_group;" ::: "memory");
    #pragma unroll
    for (int rr = 0; rr < 2; rr++) {
        const __half* B = g_Wh + (rbase + rr) * 16384;
        #pragma unroll
        for (int it = 0; it < 16; it++) {
            int id = it * 128 + tid;
            int row = id >> 4, c = id & 15;
            cp16(bb[rr] + row * 256 + ((c ^ (row & 7)) * 16), B + row * 128 + c * 8, 16u);
        }
        asm volatile("cp.async.commit_group;" ::: "memory");
    }

    uint32_t arow = (uint32_t)(wm * 64 + (lane & 15));
    uint32_t axor = arow & 7;
    uint32_t alh  = (uint32_t)(lane >> 4);
    uint32_t abase_l = ab + arow * 256;
    uint32_t brow_l  = (uint32_t)(lane & 15);
    uint32_t bxor    = (uint32_t)(lane & 7);

    asm volatile("cp.async.wait_group 1;" ::: "memory");
    __syncthreads();

    #pragma unroll
    for (int rr = 0; rr < 2; rr++) {
        if (rr == 1) {
            asm volatile("cp.async.wait_group 0;" ::: "memory");
            __syncthreads();
        }
        uint32_t bsb = bb[rr];

        float c[4][8][4];
        #pragma unroll
        for (int i = 0; i < 4; i++)
            #pragma unroll
            for (int j = 0; j < 8; j++)
                c[i][j][0] = c[i][j][1] = c[i][j][2] = c[i][j][3] = 0.f;

        #pragma unroll
        for (int k16 = 0; k16 < 8; k16++) {
            uint32_t a[4][4], b[8][2];
            uint32_t ach = (uint32_t)(k16 * 2) + alh;
            #pragma unroll
            for (int i = 0; i < 4; i++) {
                uint32_t ad = abase_l + (uint32_t)(i * 16 * 256) +
                              ((ach ^ axor) * 16);
                asm volatile("ldmatrix.sync.aligned.m8n8.x4.shared.b16 "
                             "{%0,%1,%2,%3}, [%4];"
                             : "=r"(a[i][0]), "=r"(a[i][1]),
                               "=r"(a[i][2]), "=r"(a[i][3])
                             : "r"(ad));
            }
            uint32_t brow = (uint32_t)(k16 * 16) + brow_l;
            #pragma unroll
            for (int p = 0; p < 4; p++) {
                uint32_t nch = (uint32_t)(wn * 8 + p * 2) + alh;
                uint32_t bd = bsb + brow * 256 + ((nch ^ bxor) * 16);
                asm volatile("ldmatrix.sync.aligned.m8n8.x4.trans.shared.b16 "
                             "{%0,%1,%2,%3}, [%4];"
                             : "=r"(b[p*2][0]), "=r"(b[p*2][1]),
                               "=r"(b[p*2+1][0]), "=r"(b[p*2+1][1])
                             : "r"(bd));
            }
            #pragma unroll
            for (int i = 0; i < 4; i++)
                #pragma unroll
                for (int j = 0; j < 8; j++)
                    asm volatile(
                        "mma.sync.aligned.m16n8k16.row.col.f32.f16.f16.f32 "
                        "{%0,%1,%2,%3}, {%4,%5,%6,%7}, {%8,%9}, {%0,%1,%2,%3};"
                        : "+f"(c[i][j][0]), "+f"(c[i][j][1]),
                          "+f"(c[i][j][2]), "+f"(c[i][j][3])
                        : "r"(a[i][0]), "r"(a[i][1]), "r"(a[i][2]), "r"(a[i][3]),
                          "r"(b[j][0]), "r"(b[j][1]));
        }

        int grp = lane >> 2, tg = lane & 3;
        uint32_t* H = (uint32_t*)g_Hh + (size_t)(rbase + rr) * NNODES * 64;
        #pragma unroll
        for (int i = 0; i < 4; i++) {
            int row0 = m0 + wm * 64 + i * 16 + grp;
            #pragma unroll
            for (int j = 0; j < 8; j++) {
                int nc2 = (wn * 64 + j * 8 + tg * 2) >> 1;
                __half2 lo = __floats2half2_rn(c[i][j][0], c[i][j][1]);
                __half2 hi = __floats2half2_rn(c[i][j][2], c[i][j][3]);
                if (row0 < NNODES)
                    H[(size_t)row0 * 64 + nc2] = *(uint32_t*)&lo;
                if (row0 + 8 < NNODES)
                    H[(size_t)(row0 + 8) * 64 + nc2] = *(uint32_t*)&hi;
            }
        }
    }
}

// ---------------------------------------------------------------------------
// Scatter (half): warp per node; ONE contiguous edge range covering the 4
// relations (CSR indexed n*8+r; edge carries flat H-row index). Unroll x4.
// ---------------------------------------------------------------------------
__global__ void __launch_bounds__(256) k_scatter(int half, float* __restrict__ out) {
    int n = blockIdx.x * 8 + (threadIdx.x >> 5);
    int lane = threadIdx.x & 31;
    if (n >= NNODES) return;

    int base = n * 8 + half * 4;
    int j = __ldg(&g_off[base]);
    int e = __ldg(&g_off[base + 4]);

    float4 acc;
    if (half == 0) acc = make_float4(0.f, 0.f, 0.f, 0.f);
    else           acc = ((float4*)out)[(size_t)n * 32 + lane];

    const uint2* H2 = (const uint2*)g_Hh;

    for (; j + 3 < e; j += 4) {
        int2 e0 = __ldg(&g_edge[j]);
        int2 e1 = __ldg(&g_edge[j + 1]);
        int2 e2 = __ldg(&g_edge[j + 2]);
        int2 e3 = __ldg(&g_edge[j + 3]);
        uint2 p0 = __ldg(&H2[(size_t)e0.x * 32 + lane]);
        uint2 p1 = __ldg(&H2[(size_t)e1.x * 32 + lane]);
        uint2 p2 = __ldg(&H2[(size_t)e2.x * 32 + lane]);
        uint2 p3 = __ldg(&H2[(size_t)e3.x * 32 + lane]);
        float v0 = __int_as_float(e0.y), v1 = __int_as_float(e1.y);
        float v2 = __int_as_float(e2.y), v3 = __int_as_float(e3.y);
        float2 x0 = __half22float2(*(__half2*)&p0.x), y0 = __half22float2(*(__half2*)&p0.y);
        float2 x1 = __half22float2(*(__half2*)&p1.x), y1 = __half22float2(*(__half2*)&p1.y);
        float2 x2 = __half22float2(*(__half2*)&p2.x), y2 = __half22float2(*(__half2*)&p2.y);
        float2 x3 = __half22float2(*(__half2*)&p3.x), y3 = __half22float2(*(__half2*)&p3.y);
        acc.x += v0 * x0.x + v1 * x1.x + v2 * x2.x + v3 * x3.x;
        acc.y += v0 * x0.y + v1 * x1.y + v2 * x2.y + v3 * x3.y;
        acc.z += v0 * y0.x + v1 * y1.x + v2 * y2.x + v3 * y3.x;
        acc.w += v0 * y0.y + v1 * y1.y + v2 * y2.y + v3 * y3.y;
    }
    if (j + 1 < e) {
        int2 e0 = __ldg(&g_edge[j]);
        int2 e1 = __ldg(&g_edge[j + 1]);
        uint2 p0 = __ldg(&H2[(size_t)e0.x * 32 + lane]);
        uint2 p1 = __ldg(&H2[(size_t)e1.x * 32 + lane]);
        float v0 = __int_as_float(e0.y), v1 = __int_as_float(e1.y);
        float2 x0 = __half22float2(*(__half2*)&p0.x), y0 = __half22float2(*(__half2*)&p0.y);
        float2 x1 = __half22float2(*(__half2*)&p1.x), y1 = __half22float2(*(__half2*)&p1.y);
        acc.x += v0 * x0.x + v1 * x1.x;
        acc.y += v0 * x0.y + v1 * x1.y;
        acc.z += v0 * y0.x + v1 * y1.x;
        acc.w += v0 * y0.y + v1 * y1.y;
        j += 2;
    }
    if (j < e) {
        int2 e0 = __ldg(&g_edge[j]);
        uint2 p = __ldg(&H2[(size_t)e0.x * 32 + lane]);
        float v = __int_as_float(e0.y);
        float2 x = __half22float2(*(__half2*)&p.x), y = __half22float2(*(__half2*)&p.y);
        acc.x += v * x.x; acc.y += v * x.y;
        acc.z += v * y.x; acc.w += v * y.y;
    }
    ((float4*)out)[(size_t)n * 32 + lane] = acc;
}

// ---------------------------------------------------------------------------
// Streams/events + smem opt-in (host objects, pre-main)
// ---------------------------------------------------------------------------
static cudaStream_t s2 = nullptr;
static cudaEvent_t  evFork, evG0, evS0;
static bool g_ok = false;

#define GEMM_SMEM 98304

namespace {
struct StreamInit {
    StreamInit() {
        cudaFuncSetAttribute((const void*)k_gemm,
                             cudaFuncAttributeMaxDynamicSharedMemorySize, GEMM_SMEM);
        if (cudaStreamCreateWithFlags(&s2, cudaStreamNonBlocking) != cudaSuccess) return;
        if (cudaEventCreateWithFlags(&evFork, cudaEventDisableTiming) != cudaSuccess) return;
        if (cudaEventCreateWithFlags(&evG0,   cudaEventDisableTiming) != cudaSuccess) return;
        if (cudaEventCreateWithFlags(&evS0,   cudaEventDisableTiming) != cudaSuccess) return;
        g_ok = true;
    }
};
static StreamInit g_si;
}

extern "C" void kernel_launch(void* const* d_in, const int* in_sizes, int n_in,
                              void* d_out, int out_size) {
    const float* inp  = (const float*)d_in[0];
    const int*   src  = (const int*)  d_in[1];
    const int*   dst  = (const int*)  d_in[2];
    const float* vals = (const float*)d_in[3];
    const float* W    = (const float*)d_in[4];
    float* out = (float*)d_out;

    cudaFuncSetAttribute((const void*)k_gemm,
                         cudaFuncAttributeMaxDynamicSharedMemorySize, GEMM_SMEM);

    const int SCAN_BLKS = (NIDX + 4095) / 4096;   // 98
    const int PREP_BLKS = (INPSZ / 2 + 255) / 256;
    dim3 ggrid((NNODES + 127) / 128, 2);          // 391 x 2 (4 rel per launch)
    int  sgrid = (NNODES + 7) / 8;                // warp per node

    if (g_ok) {
        cudaEventRecord(evFork, 0);
        cudaStreamWaitEvent(s2, evFork, 0);

        k_prep<<<PREP_BLKS, 256>>>((const float2*)inp, (const float2*)W);   // 0
        k_zero<<<(NIDX + 255) / 256, 256, 0, s2>>>();                        // 1
        k_hist<<<(RE + 255) / 256, 256, 0, s2>>>(dst);                       // 2
        k_gemm<<<ggrid, 128, GEMM_SMEM>>>(0);                                // 3
        cudaEventRecord(evG0, 0);
        k_scanA<<<SCAN_BLKS, 1024, 0, s2>>>();                               // 4
        k_scanB<<<1, 128, 0, s2>>>(SCAN_BLKS);                               // 5
        k_scanC<<<SCAN_BLKS, 1024, 0, s2>>>();                               // 6
        k_fill <<<(RE + 255) / 256, 256, 0, s2>>>(dst, src, vals);           // 7
        k_gemm<<<ggrid, 128, GEMM_SMEM>>>(1);                                // 8
        cudaStreamWaitEvent(s2, evG0, 0);
        k_scatter<<<sgrid, 256, 0, s2>>>(0, out);                            // 9
        cudaEventRecord(evS0, s2);
        cudaStreamWaitEvent(0, evS0, 0);
        k_scatter<<<sgrid, 256>>>(1, out);                                   // 10
    } else {
        k_prep<<<PREP_BLKS, 256>>>((const float2*)inp, (const float2*)W);
        k_zero<<<(NIDX + 255) / 256, 256>>>();
        k_hist<<<(RE + 255) / 256, 256>>>(dst);
        k_gemm<<<ggrid, 128, GEMM_SMEM>>>(0);
        k_scanA<<<SCAN_BLKS, 1024>>>();
        k_scanB<<<1, 128>>>(SCAN_BLKS);
        k_scanC<<<SCAN_BLKS, 1024>>>();
        k_fill <<<(RE + 255) / 256, 256>>>(dst, src, vals);
        k_gemm<<<ggrid, 128, GEMM_SMEM>>>(1);
        k_scatter<<<sgrid, 256>>>(0, out);
        k_scatter<<<sgrid, 256>>>(1, out);
    }
}